// round 5
// baseline (speedup 1.0000x reference)
#include <cuda_runtime.h>

#define NGMAX 8192
#define DCOLS 128
__device__ float g_Z[NGMAX];

__global__ void zero_kernel(float4* out4, int n4, int ng4) {
    int i = blockIdx.x * blockDim.x + threadIdx.x;
    float4 z = make_float4(0.f, 0.f, 0.f, 0.f);
    if (i < n4) out4[i] = z;
    if (i < ng4) reinterpret_cast<float4*>(g_Z)[i] = z;
}

__device__ __forceinline__ float warp_bcast_sum(float p) {
    p += __shfl_xor_sync(0xFFFFFFFFu, p, 16);
    p += __shfl_xor_sync(0xFFFFFFFFu, p, 8);
    p += __shfl_xor_sync(0xFFFFFFFFu, p, 4);
    p += __shfl_xor_sync(0xFFFFFFFFu, p, 2);
    p += __shfl_xor_sync(0xFFFFFFFFu, p, 1);
    return p;
}

// Reduce 4 independent values across the warp with 6 shfls, exp once,
// broadcast all 4 exp'd results back with 3 shfls.
// On return l0..l3 = expf(full_sum(p0..p3) + bias) on every lane.
__device__ __forceinline__ void quad_reduce_exp(
    float p0, float p1, float p2, float p3, float bias, int lane,
    float& l0, float& l1, float& l2, float& l3)
{
    const unsigned F = 0xFFFFFFFFu;
    // stage 1 (mask 1): fold (p0,p1) and (p2,p3)
    float a   = (lane & 1) ? p0 : p1;
    float v01 = ((lane & 1) ? p1 : p0) + __shfl_xor_sync(F, a, 1);
    float c   = (lane & 1) ? p2 : p3;
    float v23 = ((lane & 1) ? p3 : p2) + __shfl_xor_sync(F, c, 1);
    // stage 2 (mask 2): fold (v01, v23)
    float e = (lane & 2) ? v01 : v23;
    float v = ((lane & 2) ? v23 : v01) + __shfl_xor_sync(F, e, 2);
    // stages 3-5: plain butterfly; lane now owns row (lane&3)
    v += __shfl_xor_sync(F, v, 4);
    v += __shfl_xor_sync(F, v, 8);
    v += __shfl_xor_sync(F, v, 16);
    float myl = __expf(v + bias);          // one MUFU per lane
    // broadcast the 4 distinct values to every lane
    float t1 = __shfl_xor_sync(F, myl, 1); // row (lane&3)^1
    float t2 = __shfl_xor_sync(F, myl, 2); // row (lane&3)^2
    float t3 = __shfl_xor_sync(F, t1, 2);  // row (lane&3)^3
    int q = lane & 3;
    l0 = (q == 0) ? myl : (q == 1) ? t1 : (q == 2) ? t2 : t3;
    l1 = (q == 1) ? myl : (q == 0) ? t1 : (q == 3) ? t2 : t3;
    l2 = (q == 2) ? myl : (q == 3) ? t1 : (q == 0) ? t2 : t3;
    l3 = (q == 3) ? myl : (q == 2) ? t1 : (q == 1) ? t2 : t3;
}

// One warp per chunk of rows_per_warp contiguous rows.
// Lane k holds columns [4k, 4k+4) as a float4. 8-row software pipeline.
__global__ void agg_kernel(const float* __restrict__ H,
                           const int*   __restrict__ batch,
                           const float* __restrict__ w,
                           const float* __restrict__ b,
                           float* __restrict__ out,
                           int V, int rows_per_warp) {
    int warp = (blockIdx.x * blockDim.x + threadIdx.x) >> 5;
    int lane = threadIdx.x & 31;

    long start = (long)warp * rows_per_warp;
    if (start >= V) return;
    long end = start + rows_per_warp;
    if (end > V) end = V;

    float4 w4 = reinterpret_cast<const float4*>(w)[lane];
    float bias = b[0];

    float4 acc = make_float4(0.f, 0.f, 0.f, 0.f);
    float  zacc = 0.f;
    int    seg  = batch[start];

#define FLUSH()                                                         \
    do {                                                                \
        float* o = out + (long)seg * DCOLS + lane * 4;                  \
        atomicAdd(o + 0, acc.x);                                        \
        atomicAdd(o + 1, acc.y);                                        \
        atomicAdd(o + 2, acc.z);                                        \
        atomicAdd(o + 3, acc.w);                                        \
        if (lane == 0) atomicAdd(&g_Z[seg], zacc);                      \
        acc = make_float4(0.f, 0.f, 0.f, 0.f);                          \
        zacc = 0.f;                                                     \
    } while (0)

#define ACCUM(s_, h_, l_)                                               \
    do {                                                                \
        if ((s_) != seg) { FLUSH(); seg = (s_); }                       \
        acc.x += (l_) * (h_).x;                                         \
        acc.y += (l_) * (h_).y;                                         \
        acc.z += (l_) * (h_).z;                                         \
        acc.w += (l_) * (h_).w;                                         \
        zacc  += (l_);                                                  \
    } while (0)

    long r = start;
    for (; r + 8 <= end; r += 8) {
        // front-batched independent loads (MLP_p1 ~ 10)
        int4   ba = *reinterpret_cast<const int4*>(batch + r);
        int4   bb = *reinterpret_cast<const int4*>(batch + r + 4);
        float4 h0 = reinterpret_cast<const float4*>(H + (r + 0) * DCOLS)[lane];
        float4 h1 = reinterpret_cast<const float4*>(H + (r + 1) * DCOLS)[lane];
        float4 h2 = reinterpret_cast<const float4*>(H + (r + 2) * DCOLS)[lane];
        float4 h3 = reinterpret_cast<const float4*>(H + (r + 3) * DCOLS)[lane];
        float4 h4 = reinterpret_cast<const float4*>(H + (r + 4) * DCOLS)[lane];
        float4 h5 = reinterpret_cast<const float4*>(H + (r + 5) * DCOLS)[lane];
        float4 h6 = reinterpret_cast<const float4*>(H + (r + 6) * DCOLS)[lane];
        float4 h7 = reinterpret_cast<const float4*>(H + (r + 7) * DCOLS)[lane];

        float p0 = h0.x * w4.x + h0.y * w4.y + h0.z * w4.z + h0.w * w4.w;
        float p1 = h1.x * w4.x + h1.y * w4.y + h1.z * w4.z + h1.w * w4.w;
        float p2 = h2.x * w4.x + h2.y * w4.y + h2.z * w4.z + h2.w * w4.w;
        float p3 = h3.x * w4.x + h3.y * w4.y + h3.z * w4.z + h3.w * w4.w;
        float p4 = h4.x * w4.x + h4.y * w4.y + h4.z * w4.z + h4.w * w4.w;
        float p5 = h5.x * w4.x + h5.y * w4.y + h5.z * w4.z + h5.w * w4.w;
        float p6 = h6.x * w4.x + h6.y * w4.y + h6.z * w4.z + h6.w * w4.w;
        float p7 = h7.x * w4.x + h7.y * w4.y + h7.z * w4.z + h7.w * w4.w;

        // two independent 4-row reduction chains (latencies overlap)
        float l0, l1, l2, l3, l4, l5, l6, l7;
        quad_reduce_exp(p0, p1, p2, p3, bias, lane, l0, l1, l2, l3);
        quad_reduce_exp(p4, p5, p6, p7, bias, lane, l4, l5, l6, l7);

        ACCUM(ba.x, h0, l0);
        ACCUM(ba.y, h1, l1);
        ACCUM(ba.z, h2, l2);
        ACCUM(ba.w, h3, l3);
        ACCUM(bb.x, h4, l4);
        ACCUM(bb.y, h5, l5);
        ACCUM(bb.z, h6, l6);
        ACCUM(bb.w, h7, l7);
    }

    // tail
    for (; r < end; ++r) {
        int s = batch[r];
        float4 h = reinterpret_cast<const float4*>(H + r * DCOLS)[lane];
        float p = h.x * w4.x + h.y * w4.y + h.z * w4.z + h.w * w4.w;
        p = warp_bcast_sum(p);
        float l = __expf(p + bias);
        ACCUM(s, h, l);
    }

    FLUSH();
#undef ACCUM
#undef FLUSH
}

__global__ void div_kernel(float4* out4, int n4) {
    int i = blockIdx.x * blockDim.x + threadIdx.x;
    if (i < n4) {
        float z = g_Z[i >> 5];  // (i*4)/128 -> graph id
        float4 v = out4[i];
        if (z > 0.f) {
            float inv = 1.0f / z;
            v.x *= inv; v.y *= inv; v.z *= inv; v.w *= inv;
        } else {
            v = make_float4(0.f, 0.f, 0.f, 0.f);
        }
        out4[i] = v;
    }
}

extern "C" void kernel_launch(void* const* d_in, const int* in_sizes, int n_in,
                              void* d_out, int out_size) {
    const float* H     = (const float*)d_in[0];
    const int*   batch = (const int*)d_in[1];
    const float* w     = (const float*)d_in[2];
    const float* b     = (const float*)d_in[3];
    float*       out   = (float*)d_out;

    int V  = in_sizes[1];           // number of rows
    int ng = out_size / DCOLS;      // number of graphs
    int n4 = out_size / 4;
    int ng4 = (ng + 3) / 4;

    {
        int n = n4 > ng4 ? n4 : ng4;
        int threads = 256;
        int blocks = (n + threads - 1) / threads;
        zero_kernel<<<blocks, threads>>>((float4*)out, n4, ng4);
    }
    {
        const int rows_per_warp = 128;
        long warps = ((long)V + rows_per_warp - 1) / rows_per_warp;
        int threads = 256;
        long blocks = (warps * 32 + threads - 1) / threads;
        agg_kernel<<<(int)blocks, threads>>>(H, batch, w, b, out, V, rows_per_warp);
    }
    {
        int threads = 256;
        int blocks = (n4 + threads - 1) / threads;
        div_kernel<<<blocks, threads>>>((float4*)out, n4);
    }
}

// round 7
// speedup vs baseline: 1.2366x; 1.2366x over previous
#include <cuda_runtime.h>

#define DCOLS 128

// One block per graph (segment). batch is sorted, so graph g owns the
// contiguous row range [lower_bound(g), lower_bound(g+1)).
// 8 warps/block; warp wid processes rows base+wid*4 .. +3 per 32-row tile,
// lane k holds columns [4k, 4k+4) as a float4 (R3-proven inner loop).
__global__ void __launch_bounds__(256)
seg_kernel(const float* __restrict__ H,
           const int*   __restrict__ batch,
           const float* __restrict__ w,
           const float* __restrict__ b,
           float* __restrict__ out,
           int V) {
    __shared__ long  s_bounds[2];
    __shared__ float s_acc[8][DCOLS];
    __shared__ float s_z[8];
    __shared__ float s_scale;

    int g    = blockIdx.x;
    int tid  = threadIdx.x;
    int wid  = tid >> 5;
    int lane = tid & 31;

    if (tid < 2) {
        int target = g + tid;
        long lo = 0, hi = V;
        while (lo < hi) {
            long mid = (lo + hi) >> 1;
            if (batch[mid] < target) lo = mid + 1; else hi = mid;
        }
        s_bounds[tid] = lo;
    }
    __syncthreads();
    long segA = s_bounds[0];
    long segB = s_bounds[1];
    long n    = segB - segA;

    float4 w4   = reinterpret_cast<const float4*>(w)[lane];
    float  bias = b[0];

    float4 acc  = make_float4(0.f, 0.f, 0.f, 0.f);
    float  zacc = 0.f;

    // full 32-row tiles: warp wid handles 4 contiguous rows per tile
    long full_end = segA + (n & ~31L);
    for (long r = segA + wid * 4; r < full_end; r += 32) {
        float4 h0 = reinterpret_cast<const float4*>(H + (r + 0) * DCOLS)[lane];
        float4 h1 = reinterpret_cast<const float4*>(H + (r + 1) * DCOLS)[lane];
        float4 h2 = reinterpret_cast<const float4*>(H + (r + 2) * DCOLS)[lane];
        float4 h3 = reinterpret_cast<const float4*>(H + (r + 3) * DCOLS)[lane];

        float p0 = h0.x * w4.x + h0.y * w4.y + h0.z * w4.z + h0.w * w4.w;
        float p1 = h1.x * w4.x + h1.y * w4.y + h1.z * w4.z + h1.w * w4.w;
        float p2 = h2.x * w4.x + h2.y * w4.y + h2.z * w4.z + h2.w * w4.w;
        float p3 = h3.x * w4.x + h3.y * w4.y + h3.z * w4.z + h3.w * w4.w;

        // four independent butterfly chains — latencies overlap
        #pragma unroll
        for (int m = 16; m >= 1; m >>= 1) {
            p0 += __shfl_xor_sync(0xFFFFFFFFu, p0, m);
            p1 += __shfl_xor_sync(0xFFFFFFFFu, p1, m);
            p2 += __shfl_xor_sync(0xFFFFFFFFu, p2, m);
            p3 += __shfl_xor_sync(0xFFFFFFFFu, p3, m);
        }

        float l0 = __expf(p0 + bias);
        float l1 = __expf(p1 + bias);
        float l2 = __expf(p2 + bias);
        float l3 = __expf(p3 + bias);

        acc.x += l0 * h0.x + l1 * h1.x + l2 * h2.x + l3 * h3.x;
        acc.y += l0 * h0.y + l1 * h1.y + l2 * h2.y + l3 * h3.y;
        acc.z += l0 * h0.z + l1 * h1.z + l2 * h2.z + l3 * h3.z;
        acc.w += l0 * h0.w + l1 * h1.w + l2 * h2.w + l3 * h3.w;
        zacc  += l0 + l1 + l2 + l3;
    }

    // tail rows (< 32): one row at a time, warps strided
    for (long r = full_end + wid; r < segB; r += 8) {
        float4 h = reinterpret_cast<const float4*>(H + r * DCOLS)[lane];
        float p = h.x * w4.x + h.y * w4.y + h.z * w4.z + h.w * w4.w;
        #pragma unroll
        for (int m = 16; m >= 1; m >>= 1)
            p += __shfl_xor_sync(0xFFFFFFFFu, p, m);
        float l = __expf(p + bias);
        acc.x += l * h.x;
        acc.y += l * h.y;
        acc.z += l * h.z;
        acc.w += l * h.w;
        zacc  += l;
    }

    // per-warp partials -> smem
    *reinterpret_cast<float4*>(&s_acc[wid][lane * 4]) = acc;
    if (lane == 0) s_z[wid] = zacc;   // zacc identical across lanes
    __syncthreads();

    if (tid == 0) {
        float Z = 0.f;
        #pragma unroll
        for (int k = 0; k < 8; ++k) Z += s_z[k];
        s_scale = (Z > 0.f) ? 1.0f / Z : 0.f;
    }

    // cross-warp column reduction (threads 0..127 own one column each)
    float colsum = 0.f;
    if (tid < DCOLS) {
        #pragma unroll
        for (int k = 0; k < 8; ++k) colsum += s_acc[k][tid];
    }
    __syncthreads();

    if (tid < DCOLS)
        out[(long)g * DCOLS + tid] = colsum * s_scale;
}

extern "C" void kernel_launch(void* const* d_in, const int* in_sizes, int n_in,
                              void* d_out, int out_size) {
    const float* H     = (const float*)d_in[0];
    const int*   batch = (const int*)d_in[1];
    const float* w     = (const float*)d_in[2];
    const float* b     = (const float*)d_in[3];
    float*       out   = (float*)d_out;

    int V  = in_sizes[1];
    int ng = out_size / DCOLS;

    seg_kernel<<<ng, 256>>>(H, batch, w, b, out, V);
}

// round 8
// speedup vs baseline: 1.3964x; 1.1292x over previous
#include <cuda_runtime.h>

#define NGMAX 8192
#define DCOLS 128
__device__ float g_Z[NGMAX];

__global__ void zero_kernel(float4* out4, int n4, int ng4) {
    int i = blockIdx.x * blockDim.x + threadIdx.x;
    float4 z = make_float4(0.f, 0.f, 0.f, 0.f);
    if (i < n4) out4[i] = z;
    if (i < ng4) reinterpret_cast<float4*>(g_Z)[i] = z;
}

__device__ __forceinline__ float warp_bcast_sum(float p) {
    p += __shfl_xor_sync(0xFFFFFFFFu, p, 16);
    p += __shfl_xor_sync(0xFFFFFFFFu, p, 8);
    p += __shfl_xor_sync(0xFFFFFFFFu, p, 4);
    p += __shfl_xor_sync(0xFFFFFFFFu, p, 2);
    p += __shfl_xor_sync(0xFFFFFFFFu, p, 1);
    return p;
}

// One warp per chunk of rows_per_warp contiguous rows.
// Lane k holds columns [4k, 4k+4) as a float4.
// 8-row front-batched loads, two 4-row compute phases (R3 butterflies).
__global__ void agg_kernel(const float* __restrict__ H,
                           const int*   __restrict__ batch,
                           const float* __restrict__ w,
                           const float* __restrict__ b,
                           float* __restrict__ out,
                           int V, int rows_per_warp) {
    int warp = (blockIdx.x * blockDim.x + threadIdx.x) >> 5;
    int lane = threadIdx.x & 31;

    long start = (long)warp * rows_per_warp;
    if (start >= V) return;
    long end = start + rows_per_warp;
    if (end > V) end = V;

    float4 w4 = reinterpret_cast<const float4*>(w)[lane];
    float bias = b[0];

    float4 acc = make_float4(0.f, 0.f, 0.f, 0.f);
    float  zacc = 0.f;
    int    seg  = batch[start];

#define FLUSH()                                                         \
    do {                                                                \
        float* o = out + (long)seg * DCOLS + lane * 4;                  \
        atomicAdd(o + 0, acc.x);                                        \
        atomicAdd(o + 1, acc.y);                                        \
        atomicAdd(o + 2, acc.z);                                        \
        atomicAdd(o + 3, acc.w);                                        \
        if (lane == 0) atomicAdd(&g_Z[seg], zacc);                      \
        acc = make_float4(0.f, 0.f, 0.f, 0.f);                          \
        zacc = 0.f;                                                     \
    } while (0)

#define ACCUM(s_, h_, l_)                                               \
    do {                                                                \
        if ((s_) != seg) { FLUSH(); seg = (s_); }                       \
        acc.x += (l_) * (h_).x;                                         \
        acc.y += (l_) * (h_).y;                                         \
        acc.z += (l_) * (h_).z;                                         \
        acc.w += (l_) * (h_).w;                                         \
        zacc  += (l_);                                                  \
    } while (0)

    long r = start;
    for (; r + 8 <= end; r += 8) {
        // ---- front-batched independent loads: MLP_p1 ~ 10 ----
        int4   ba = *reinterpret_cast<const int4*>(batch + r);
        int4   bb = *reinterpret_cast<const int4*>(batch + r + 4);
        float4 h0 = reinterpret_cast<const float4*>(H + (r + 0) * DCOLS)[lane];
        float4 h1 = reinterpret_cast<const float4*>(H + (r + 1) * DCOLS)[lane];
        float4 h2 = reinterpret_cast<const float4*>(H + (r + 2) * DCOLS)[lane];
        float4 h3 = reinterpret_cast<const float4*>(H + (r + 3) * DCOLS)[lane];
        float4 h4 = reinterpret_cast<const float4*>(H + (r + 4) * DCOLS)[lane];
        float4 h5 = reinterpret_cast<const float4*>(H + (r + 5) * DCOLS)[lane];
        float4 h6 = reinterpret_cast<const float4*>(H + (r + 6) * DCOLS)[lane];
        float4 h7 = reinterpret_cast<const float4*>(H + (r + 7) * DCOLS)[lane];

        // ---- phase 1: rows 0-3 (h4-h7 still in flight / live) ----
        float p0 = h0.x * w4.x + h0.y * w4.y + h0.z * w4.z + h0.w * w4.w;
        float p1 = h1.x * w4.x + h1.y * w4.y + h1.z * w4.z + h1.w * w4.w;
        float p2 = h2.x * w4.x + h2.y * w4.y + h2.z * w4.z + h2.w * w4.w;
        float p3 = h3.x * w4.x + h3.y * w4.y + h3.z * w4.z + h3.w * w4.w;
        #pragma unroll
        for (int m = 16; m >= 1; m >>= 1) {
            p0 += __shfl_xor_sync(0xFFFFFFFFu, p0, m);
            p1 += __shfl_xor_sync(0xFFFFFFFFu, p1, m);
            p2 += __shfl_xor_sync(0xFFFFFFFFu, p2, m);
            p3 += __shfl_xor_sync(0xFFFFFFFFu, p3, m);
        }
        float l0 = __expf(p0 + bias);
        float l1 = __expf(p1 + bias);
        float l2 = __expf(p2 + bias);
        float l3 = __expf(p3 + bias);
        ACCUM(ba.x, h0, l0);
        ACCUM(ba.y, h1, l1);
        ACCUM(ba.z, h2, l2);
        ACCUM(ba.w, h3, l3);

        // ---- phase 2: rows 4-7 (h0-h3 registers now dead) ----
        float p4 = h4.x * w4.x + h4.y * w4.y + h4.z * w4.z + h4.w * w4.w;
        float p5 = h5.x * w4.x + h5.y * w4.y + h5.z * w4.z + h5.w * w4.w;
        float p6 = h6.x * w4.x + h6.y * w4.y + h6.z * w4.z + h6.w * w4.w;
        float p7 = h7.x * w4.x + h7.y * w4.y + h7.z * w4.z + h7.w * w4.w;
        #pragma unroll
        for (int m = 16; m >= 1; m >>= 1) {
            p4 += __shfl_xor_sync(0xFFFFFFFFu, p4, m);
            p5 += __shfl_xor_sync(0xFFFFFFFFu, p5, m);
            p6 += __shfl_xor_sync(0xFFFFFFFFu, p6, m);
            p7 += __shfl_xor_sync(0xFFFFFFFFu, p7, m);
        }
        float l4 = __expf(p4 + bias);
        float l5 = __expf(p5 + bias);
        float l6 = __expf(p6 + bias);
        float l7 = __expf(p7 + bias);
        ACCUM(bb.x, h4, l4);
        ACCUM(bb.y, h5, l5);
        ACCUM(bb.z, h6, l6);
        ACCUM(bb.w, h7, l7);
    }

    // tail
    for (; r < end; ++r) {
        int s = batch[r];
        float4 h = reinterpret_cast<const float4*>(H + r * DCOLS)[lane];
        float p = h.x * w4.x + h.y * w4.y + h.z * w4.z + h.w * w4.w;
        p = warp_bcast_sum(p);
        float l = __expf(p + bias);
        ACCUM(s, h, l);
    }

    FLUSH();
#undef ACCUM
#undef FLUSH
}

__global__ void div_kernel(float4* out4, int n4) {
    int i = blockIdx.x * blockDim.x + threadIdx.x;
    if (i < n4) {
        float z = g_Z[i >> 5];  // (i*4)/128 -> graph id
        float4 v = out4[i];
        if (z > 0.f) {
            float inv = 1.0f / z;
            v.x *= inv; v.y *= inv; v.z *= inv; v.w *= inv;
        } else {
            v = make_float4(0.f, 0.f, 0.f, 0.f);
        }
        out4[i] = v;
    }
}

extern "C" void kernel_launch(void* const* d_in, const int* in_sizes, int n_in,
                              void* d_out, int out_size) {
    const float* H     = (const float*)d_in[0];
    const int*   batch = (const int*)d_in[1];
    const float* w     = (const float*)d_in[2];
    const float* b     = (const float*)d_in[3];
    float*       out   = (float*)d_out;

    int V  = in_sizes[1];           // number of rows
    int ng = out_size / DCOLS;      // number of graphs
    int n4 = out_size / 4;
    int ng4 = (ng + 3) / 4;

    {
        int n = n4 > ng4 ? n4 : ng4;
        int threads = 256;
        int blocks = (n + threads - 1) / threads;
        zero_kernel<<<blocks, threads>>>((float4*)out, n4, ng4);
    }
    {
        const int rows_per_warp = 128;
        long warps = ((long)V + rows_per_warp - 1) / rows_per_warp;
        int threads = 256;
        long blocks = (warps * 32 + threads - 1) / threads;
        agg_kernel<<<(int)blocks, threads>>>(H, batch, w, b, out, V, rows_per_warp);
    }
    {
        int threads = 256;
        int blocks = (n4 + threads - 1) / threads;
        div_kernel<<<blocks, threads>>>((float4*)out, n4);
    }
}

// round 9
// speedup vs baseline: 1.5528x; 1.1120x over previous
#include <cuda_runtime.h>

#define NGMAX 4096
#define DCOLS 128
__device__ float g_Z[NGMAX];                 // zero-init at load; reset by fin_kernel
__device__ float g_S[NGMAX * DCOLS];         // zero-init at load; reset by fin_kernel

__device__ __forceinline__ float warp_bcast_sum(float p) {
    p += __shfl_xor_sync(0xFFFFFFFFu, p, 16);
    p += __shfl_xor_sync(0xFFFFFFFFu, p, 8);
    p += __shfl_xor_sync(0xFFFFFFFFu, p, 4);
    p += __shfl_xor_sync(0xFFFFFFFFu, p, 2);
    p += __shfl_xor_sync(0xFFFFFFFFu, p, 1);
    return p;
}

// One warp per chunk of rows_per_warp contiguous rows.
// Lane k holds columns [4k, 4k+4) as a float4. 4-row software pipeline
// (R3-proven form). Accumulates into device scratch g_S / g_Z.
__global__ void agg_kernel(const float* __restrict__ H,
                           const int*   __restrict__ batch,
                           const float* __restrict__ w,
                           const float* __restrict__ b,
                           int V, int rows_per_warp) {
    int warp = (blockIdx.x * blockDim.x + threadIdx.x) >> 5;
    int lane = threadIdx.x & 31;

    long start = (long)warp * rows_per_warp;
    if (start >= V) return;
    long end = start + rows_per_warp;
    if (end > V) end = V;

    float4 w4 = reinterpret_cast<const float4*>(w)[lane];
    float bias = b[0];

    float4 acc = make_float4(0.f, 0.f, 0.f, 0.f);
    float  zacc = 0.f;
    int    seg  = batch[start];

#define FLUSH()                                                         \
    do {                                                                \
        float* o = g_S + (long)seg * DCOLS + lane * 4;                  \
        atomicAdd(o + 0, acc.x);                                        \
        atomicAdd(o + 1, acc.y);                                        \
        atomicAdd(o + 2, acc.z);                                        \
        atomicAdd(o + 3, acc.w);                                        \
        if (lane == 0) atomicAdd(&g_Z[seg], zacc);                      \
        acc = make_float4(0.f, 0.f, 0.f, 0.f);                          \
        zacc = 0.f;                                                     \
    } while (0)

#define ACCUM(s_, h_, l_)                                               \
    do {                                                                \
        if ((s_) != seg) { FLUSH(); seg = (s_); }                       \
        acc.x += (l_) * (h_).x;                                         \
        acc.y += (l_) * (h_).y;                                         \
        acc.z += (l_) * (h_).z;                                         \
        acc.w += (l_) * (h_).w;                                         \
        zacc  += (l_);                                                  \
    } while (0)

    long r = start;
    for (; r + 4 <= end; r += 4) {
        // front-batched independent loads (MLP); streaming hint: H read once
        int4   bv = *reinterpret_cast<const int4*>(batch + r);
        float4 h0 = __ldcs(&reinterpret_cast<const float4*>(H + (r + 0) * DCOLS)[lane]);
        float4 h1 = __ldcs(&reinterpret_cast<const float4*>(H + (r + 1) * DCOLS)[lane]);
        float4 h2 = __ldcs(&reinterpret_cast<const float4*>(H + (r + 2) * DCOLS)[lane]);
        float4 h3 = __ldcs(&reinterpret_cast<const float4*>(H + (r + 3) * DCOLS)[lane]);

        float p0 = h0.x * w4.x + h0.y * w4.y + h0.z * w4.z + h0.w * w4.w;
        float p1 = h1.x * w4.x + h1.y * w4.y + h1.z * w4.z + h1.w * w4.w;
        float p2 = h2.x * w4.x + h2.y * w4.y + h2.z * w4.z + h2.w * w4.w;
        float p3 = h3.x * w4.x + h3.y * w4.y + h3.z * w4.z + h3.w * w4.w;

        // four independent butterfly chains — latencies overlap
        #pragma unroll
        for (int m = 16; m >= 1; m >>= 1) {
            p0 += __shfl_xor_sync(0xFFFFFFFFu, p0, m);
            p1 += __shfl_xor_sync(0xFFFFFFFFu, p1, m);
            p2 += __shfl_xor_sync(0xFFFFFFFFu, p2, m);
            p3 += __shfl_xor_sync(0xFFFFFFFFu, p3, m);
        }

        float l0 = __expf(p0 + bias);
        float l1 = __expf(p1 + bias);
        float l2 = __expf(p2 + bias);
        float l3 = __expf(p3 + bias);

        ACCUM(bv.x, h0, l0);
        ACCUM(bv.y, h1, l1);
        ACCUM(bv.z, h2, l2);
        ACCUM(bv.w, h3, l3);
    }

    // tail
    for (; r < end; ++r) {
        int s = batch[r];
        float4 h = __ldcs(&reinterpret_cast<const float4*>(H + r * DCOLS)[lane]);
        float p = h.x * w4.x + h.y * w4.y + h.z * w4.z + h.w * w4.w;
        p = warp_bcast_sum(p);
        float l = __expf(p + bias);
        ACCUM(s, h, l);
    }

    FLUSH();
#undef ACCUM
#undef FLUSH
}

// out[i] = S[i] / Z[i/128]; then reset scratch to zero for the next replay.
// Thread i (float4 granularity): all 32 threads reading g_Z[g] are one warp
// (i>>5 == g constant across the warp), so lane 0 can safely re-zero after
// a __syncwarp().
__global__ void fin_kernel(float4* __restrict__ out4, int n4) {
    int i = blockIdx.x * blockDim.x + threadIdx.x;
    if (i >= n4) return;
    int g = i >> 5;                 // (i*4)/128
    float z = g_Z[g];
    float4 v = reinterpret_cast<float4*>(g_S)[i];
    if (z > 0.f) {
        float inv = 1.0f / z;
        v.x *= inv; v.y *= inv; v.z *= inv; v.w *= inv;
    } else {
        v = make_float4(0.f, 0.f, 0.f, 0.f);
    }
    out4[i] = v;
    // reset scratch for next graph replay
    reinterpret_cast<float4*>(g_S)[i] = make_float4(0.f, 0.f, 0.f, 0.f);
    __syncwarp();
    if ((i & 31) == 0) g_Z[g] = 0.f;
}

extern "C" void kernel_launch(void* const* d_in, const int* in_sizes, int n_in,
                              void* d_out, int out_size) {
    const float* H     = (const float*)d_in[0];
    const int*   batch = (const int*)d_in[1];
    const float* w     = (const float*)d_in[2];
    const float* b     = (const float*)d_in[3];
    float*       out   = (float*)d_out;

    int V  = in_sizes[1];           // number of rows
    int n4 = out_size / 4;          // float4 count (= ng*32)

    {
        const int rows_per_warp = 128;
        long warps = ((long)V + rows_per_warp - 1) / rows_per_warp;
        int threads = 256;
        long blocks = (warps * 32 + threads - 1) / threads;
        agg_kernel<<<(int)blocks, threads>>>(H, batch, w, b, V, rows_per_warp);
    }
    {
        int threads = 256;
        int blocks = (n4 + threads - 1) / threads;
        fin_kernel<<<blocks, threads>>>((float4*)out, n4);
    }
}

// round 12
// speedup vs baseline: 1.5578x; 1.0033x over previous
#include <cuda_runtime.h>

#define NGMAX 4096
#define DCOLS 128
__device__ float g_Z[NGMAX];                 // zero-init at load; reset by fin_kernel
__device__ float g_S[NGMAX * DCOLS];         // zero-init at load; reset by fin_kernel

__device__ __forceinline__ float warp_bcast_sum(float p) {
    p += __shfl_xor_sync(0xFFFFFFFFu, p, 16);
    p += __shfl_xor_sync(0xFFFFFFFFu, p, 8);
    p += __shfl_xor_sync(0xFFFFFFFFu, p, 4);
    p += __shfl_xor_sync(0xFFFFFFFFu, p, 2);
    p += __shfl_xor_sync(0xFFFFFFFFu, p, 1);
    return p;
}

// One warp per chunk of rows_per_warp contiguous rows.
// Lane k holds columns [4k, 4k+4) as a float4. 4-row software pipeline
// (R3-proven form, frozen). Accumulates into device scratch g_S / g_Z.
__global__ void agg_kernel(const float* __restrict__ H,
                           const int*   __restrict__ batch,
                           const float* __restrict__ w,
                           const float* __restrict__ b,
                           int V, int rows_per_warp) {
    int warp = (blockIdx.x * blockDim.x + threadIdx.x) >> 5;
    int lane = threadIdx.x & 31;

    long start = (long)warp * rows_per_warp;
    if (start >= V) return;
    long end = start + rows_per_warp;
    if (end > V) end = V;

    float4 w4 = reinterpret_cast<const float4*>(w)[lane];
    float bias = b[0];

    float4 acc = make_float4(0.f, 0.f, 0.f, 0.f);
    float  zacc = 0.f;
    int    seg  = batch[start];

#define FLUSH()                                                         \
    do {                                                                \
        float* o = g_S + (long)seg * DCOLS + lane * 4;                  \
        atomicAdd(o + 0, acc.x);                                        \
        atomicAdd(o + 1, acc.y);                                        \
        atomicAdd(o + 2, acc.z);                                        \
        atomicAdd(o + 3, acc.w);                                        \
        if (lane == 0) atomicAdd(&g_Z[seg], zacc);                      \
        acc = make_float4(0.f, 0.f, 0.f, 0.f);                          \
        zacc = 0.f;                                                     \
    } while (0)

#define ACCUM(s_, h_, l_)                                               \
    do {                                                                \
        if ((s_) != seg) { FLUSH(); seg = (s_); }                       \
        acc.x += (l_) * (h_).x;                                         \
        acc.y += (l_) * (h_).y;                                         \
        acc.z += (l_) * (h_).z;                                         \
        acc.w += (l_) * (h_).w;                                         \
        zacc  += (l_);                                                  \
    } while (0)

    long r = start;
    for (; r + 4 <= end; r += 4) {
        // front-batched independent loads (MLP); streaming hint: H read once
        int4   bv = *reinterpret_cast<const int4*>(batch + r);
        float4 h0 = __ldcs(&reinterpret_cast<const float4*>(H + (r + 0) * DCOLS)[lane]);
        float4 h1 = __ldcs(&reinterpret_cast<const float4*>(H + (r + 1) * DCOLS)[lane]);
        float4 h2 = __ldcs(&reinterpret_cast<const float4*>(H + (r + 2) * DCOLS)[lane]);
        float4 h3 = __ldcs(&reinterpret_cast<const float4*>(H + (r + 3) * DCOLS)[lane]);

        float p0 = h0.x * w4.x + h0.y * w4.y + h0.z * w4.z + h0.w * w4.w;
        float p1 = h1.x * w4.x + h1.y * w4.y + h1.z * w4.z + h1.w * w4.w;
        float p2 = h2.x * w4.x + h2.y * w4.y + h2.z * w4.z + h2.w * w4.w;
        float p3 = h3.x * w4.x + h3.y * w4.y + h3.z * w4.z + h3.w * w4.w;

        // four independent butterfly chains — latencies overlap
        #pragma unroll
        for (int m = 16; m >= 1; m >>= 1) {
            p0 += __shfl_xor_sync(0xFFFFFFFFu, p0, m);
            p1 += __shfl_xor_sync(0xFFFFFFFFu, p1, m);
            p2 += __shfl_xor_sync(0xFFFFFFFFu, p2, m);
            p3 += __shfl_xor_sync(0xFFFFFFFFu, p3, m);
        }

        float l0 = __expf(p0 + bias);
        float l1 = __expf(p1 + bias);
        float l2 = __expf(p2 + bias);
        float l3 = __expf(p3 + bias);

        ACCUM(bv.x, h0, l0);
        ACCUM(bv.y, h1, l1);
        ACCUM(bv.z, h2, l2);
        ACCUM(bv.w, h3, l3);
    }

    // tail
    for (; r < end; ++r) {
        int s = batch[r];
        float4 h = __ldcs(&reinterpret_cast<const float4*>(H + r * DCOLS)[lane]);
        float p = h.x * w4.x + h.y * w4.y + h.z * w4.z + h.w * w4.w;
        p = warp_bcast_sum(p);
        float l = __expf(p + bias);
        ACCUM(s, h, l);
    }

    FLUSH();
#undef ACCUM
#undef FLUSH
}

// out[i] = S[i] / Z[i/128]; then reset scratch to zero for the next replay.
// All 32 threads of a warp read the same g_Z[g] (i>>5 constant per warp),
// so lane 0 can safely re-zero it after __syncwarp().
__global__ void fin_kernel(float4* __restrict__ out4, int n4) {
    int i = blockIdx.x * blockDim.x + threadIdx.x;
    if (i >= n4) return;
    int g = i >> 5;                 // (i*4)/128
    float z = g_Z[g];
    float4 v = reinterpret_cast<float4*>(g_S)[i];
    if (z > 0.f) {
        float inv = 1.0f / z;
        v.x *= inv; v.y *= inv; v.z *= inv; v.w *= inv;
    } else {
        v = make_float4(0.f, 0.f, 0.f, 0.f);
    }
    out4[i] = v;
    // reset scratch for next graph replay
    reinterpret_cast<float4*>(g_S)[i] = make_float4(0.f, 0.f, 0.f, 0.f);
    __syncwarp();
    if ((i & 31) == 0) g_Z[g] = 0.f;
}

extern "C" void kernel_launch(void* const* d_in, const int* in_sizes, int n_in,
                              void* d_out, int out_size) {
    const float* H     = (const float*)d_in[0];
    const int*   batch = (const int*)d_in[1];
    const float* w     = (const float*)d_in[2];
    const float* b     = (const float*)d_in[3];
    float*       out   = (float*)d_out;

    int V  = in_sizes[1];           // number of rows
    int n4 = out_size / 4;          // float4 count (= ng*32)

    {
        const int rows_per_warp = 64;   // finer work quantum -> smoother waves
        long warps = ((long)V + rows_per_warp - 1) / rows_per_warp;
        int threads = 256;
        long blocks = (warps * 32 + threads - 1) / threads;
        agg_kernel<<<(int)blocks, threads>>>(H, batch, w, b, V, rows_per_warp);
    }
    {
        int threads = 512;
        int blocks = (n4 + threads - 1) / threads;
        fin_kernel<<<blocks, threads>>>((float4*)out, n4);
    }
}